// round 3
// baseline (speedup 1.0000x reference)
#include <cuda_runtime.h>

#define N_NODES 50000
#define E_EDGES 800000
#define F_INN   512
#define HIDD    128

// ---------------- scratch (no allocs allowed) ----------------
__device__ float    g_support[(size_t)N_NODES * HIDD];   // feat @ W
__device__ float    g_emb[(size_t)N_NODES * HIDD];       // segment_sum + bias
__device__ float    g_a[N_NODES];                        // dot(emb[n], w[0:128])
__device__ float    g_c[N_NODES];                        // dot(emb[n], w[128:256])
__device__ unsigned g_m[N_NODES];                        // per-row max (ordered-uint)
__device__ float    g_s[N_NODES];                        // per-row sum of exp
__device__ float    g_t[E_EDGES];                        // per-edge temp, then exp
__device__ int      g_row[E_EDGES];                      // normalized int32 rows
__device__ int      g_col[E_EDGES];                      // normalized int32 cols
__device__ int      g_is64;                              // index dtype flag

// ordered-uint encoding so unsigned atomicMax == float max
__device__ __forceinline__ unsigned enc_f(float f) {
    unsigned u = __float_as_uint(f);
    return u ^ ((u >> 31) ? 0xFFFFFFFFu : 0x80000000u);
}
__device__ __forceinline__ float dec_f(unsigned u) {
    return __uint_as_float(u ^ ((u >> 31) ? 0x80000000u : 0xFFFFFFFFu));
}

// ---------------- K-1: detect index dtype on-device ----------------
// If the buffer really is int64, the first 16 words are all in [0, N).
// If it is int32, each int64 word packs two random indices -> almost surely
// >= 2^32 for at least one of the 16 probes.
__global__ void detect_kernel(const void* __restrict__ idx) {
    const long long* p = (const long long*)idx;
    int is64 = 1;
    for (int i = 0; i < 16; i++) {
        long long v = p[i];
        if (v < 0 || v >= N_NODES) { is64 = 0; break; }
    }
    g_is64 = is64;
}

// ---------------- K-0.5: normalize indices to int32 ----------------
__global__ void convert_kernel(const void* __restrict__ idx) {
    int e = blockIdx.x * blockDim.x + threadIdx.x;
    if (e >= E_EDGES) return;
    if (g_is64) {
        const long long* p = (const long long*)idx;
        g_row[e] = (int)p[e];
        g_col[e] = (int)p[E_EDGES + e];
    } else {
        const int* p = (const int*)idx;
        g_row[e] = p[e];
        g_col[e] = p[E_EDGES + e];
    }
}

// ---------------- K1: support = feat @ gcn_w  (SGEMM 50000x512x128) ----------------
#define BM 128
#define BN 128
#define BK 16
#define TM 8
#define TN 8

__global__ __launch_bounds__(256) void gemm_kernel(const float* __restrict__ A,
                                                   const float* __restrict__ W) {
    __shared__ float As[BK][BM + 4];
    __shared__ float Bs[BK][BN];

    const int block_row = blockIdx.x * BM;
    const int tid = threadIdx.x;
    const int tx = tid & 15;   // 0..15 column group
    const int ty = tid >> 4;   // 0..15 row group

    float acc[TM][TN];
#pragma unroll
    for (int i = 0; i < TM; i++)
#pragma unroll
        for (int j = 0; j < TN; j++) acc[i][j] = 0.f;

    const int a_row  = tid >> 2;        // 0..63
    const int a_col4 = (tid & 3) * 4;   // 0,4,8,12
    const int b_row  = tid >> 5;        // 0..7
    const int b_col4 = (tid & 31) * 4;  // 0..124

    for (int k0 = 0; k0 < F_INN; k0 += BK) {
#pragma unroll
        for (int i = 0; i < 2; i++) {
            int r = block_row + a_row + i * 64;
            float4 v = make_float4(0.f, 0.f, 0.f, 0.f);
            if (r < N_NODES)
                v = *(const float4*)(A + (size_t)r * F_INN + k0 + a_col4);
            As[a_col4 + 0][a_row + i * 64] = v.x;
            As[a_col4 + 1][a_row + i * 64] = v.y;
            As[a_col4 + 2][a_row + i * 64] = v.z;
            As[a_col4 + 3][a_row + i * 64] = v.w;
        }
#pragma unroll
        for (int i = 0; i < 2; i++) {
            int kr = b_row + i * 8;
            *(float4*)&Bs[kr][b_col4] =
                *(const float4*)(W + (size_t)(k0 + kr) * HIDD + b_col4);
        }
        __syncthreads();

#pragma unroll
        for (int k = 0; k < BK; k++) {
            float ra[TM], rb[TN];
#pragma unroll
            for (int i = 0; i < TM; i++) ra[i] = As[k][ty * TM + i];
#pragma unroll
            for (int j = 0; j < TN; j++) rb[j] = Bs[k][tx * TN + j];
#pragma unroll
            for (int i = 0; i < TM; i++)
#pragma unroll
                for (int j = 0; j < TN; j++) acc[i][j] += ra[i] * rb[j];
        }
        __syncthreads();
    }

#pragma unroll
    for (int i = 0; i < TM; i++) {
        int r = block_row + ty * TM + i;
        if (r < N_NODES) {
#pragma unroll
            for (int j = 0; j < TN; j += 4) {
                float4 v = make_float4(acc[i][j], acc[i][j + 1], acc[i][j + 2], acc[i][j + 3]);
                *(float4*)(g_support + (size_t)r * HIDD + tx * TN + j) = v;
            }
        }
    }
}

// ---------------- K0: init emb with bias, zero m/s ----------------
__global__ void init_kernel(const float* __restrict__ gcn_b) {
    int i = blockIdx.x * blockDim.x + threadIdx.x;
    if (i < N_NODES * HIDD) g_emb[i] = gcn_b[i & (HIDD - 1)];
    if (i < N_NODES) { g_m[i] = 0u; g_s[i] = 0.f; }
}

// ---------------- K2: emb[row] += v * support[col]  (warp per edge) ----------------
__global__ __launch_bounds__(256) void spmm_kernel(const float* __restrict__ vals) {
    int e = blockIdx.x * 8 + (threadIdx.x >> 5);
    if (e >= E_EDGES) return;
    int lane = threadIdx.x & 31;
    int r = g_row[e];
    int c = g_col[e];
    float v = vals[e];
    float4 x = *(const float4*)(g_support + (size_t)c * HIDD + lane * 4);
    float* dst = g_emb + (size_t)r * HIDD + lane * 4;
    atomicAdd(dst + 0, v * x.x);
    atomicAdd(dst + 1, v * x.y);
    atomicAdd(dst + 2, v * x.z);
    atomicAdd(dst + 3, v * x.w);
}

// ---------------- K3: per-node dots with mlp weights (warp per node) ----------------
__global__ __launch_bounds__(256) void nodedot_kernel(const float* __restrict__ mlp_w) {
    int n = blockIdx.x * 8 + (threadIdx.x >> 5);
    if (n >= N_NODES) return;
    int lane = threadIdx.x & 31;
    float4 e4 = *(const float4*)(g_emb + (size_t)n * HIDD + lane * 4);
    float4 w1 = *(const float4*)(mlp_w + lane * 4);
    float4 w2 = *(const float4*)(mlp_w + HIDD + lane * 4);
    float da = e4.x * w1.x + e4.y * w1.y + e4.z * w1.z + e4.w * w1.w;
    float dc = e4.x * w2.x + e4.y * w2.y + e4.z * w2.z + e4.w * w2.w;
#pragma unroll
    for (int o = 16; o > 0; o >>= 1) {
        da += __shfl_xor_sync(0xFFFFFFFFu, da, o);
        dc += __shfl_xor_sync(0xFFFFFFFFu, dc, o);
    }
    if (lane == 0) { g_a[n] = da; g_c[n] = dc; }
}

// ---------------- K4: temp per edge + segment max ----------------
__global__ void edgemax_kernel(const float* __restrict__ mlp_b) {
    int e = blockIdx.x * blockDim.x + threadIdx.x;
    if (e >= E_EDGES) return;
    int r = g_row[e];
    int c = g_col[e];
    float t = g_a[r] + g_c[c] + mlp_b[0];
    g_t[e] = t;
    atomicMax(&g_m[r], enc_f(t));
}

// ---------------- K5: exp + segment sum ----------------
__global__ void edgeexp_kernel() {
    int e = blockIdx.x * blockDim.x + threadIdx.x;
    if (e >= E_EDGES) return;
    int r = g_row[e];
    float m = dec_f(g_m[r]);
    float ex = expf(g_t[e] - m);
    g_t[e] = ex;
    atomicAdd(&g_s[r], ex);
}

// ---------------- K6: normalize + add v_ori ----------------
__global__ void edgeout_kernel(const float* __restrict__ vals,
                               float* __restrict__ out) {
    int e = blockIdx.x * blockDim.x + threadIdx.x;
    if (e >= E_EDGES) return;
    int r = g_row[e];
    out[e] = vals[e] + g_t[e] / g_s[r];
}

// ---------------- launch ----------------
extern "C" void kernel_launch(void* const* d_in, const int* in_sizes, int n_in,
                              void* d_out, int out_size) {
    // Inputs in metadata order: v_ori_vals, feat, v_indices, [num_node?],
    // gcn_w, gcn_b, mlp_w, mlp_b. Index params from the END so a materialized
    // (or dropped) num_node scalar cannot shift them.
    const float* v_vals = (const float*)d_in[0];
    const float* feat   = (const float*)d_in[1];
    const void*  idx    = d_in[2];
    const float* gcn_w  = (const float*)d_in[n_in - 4];   // 512*128
    const float* gcn_b  = (const float*)d_in[n_in - 3];   // 128
    const float* mlp_w  = (const float*)d_in[n_in - 2];   // 256
    const float* mlp_b  = (const float*)d_in[n_in - 1];   // 1
    float*       out    = (float*)d_out;

    // Detect index dtype on-device, then normalize to int32 row/col arrays.
    detect_kernel<<<1, 1>>>(idx);
    convert_kernel<<<(E_EDGES + 255) / 256, 256>>>(idx);

    // K1: GEMM -> g_support
    gemm_kernel<<<(N_NODES + BM - 1) / BM, 256>>>(feat, gcn_w);

    // K0: init emb (bias), m, s
    int init_n = N_NODES * HIDD;
    init_kernel<<<(init_n + 255) / 256, 256>>>(gcn_b);

    // K2: SpMM with atomics (warp per edge)
    spmm_kernel<<<(E_EDGES + 7) / 8, 256>>>(v_vals);

    // K3: per-node MLP dots (warp per node)
    nodedot_kernel<<<(N_NODES + 7) / 8, 256>>>(mlp_w);

    // K4..K6: segment softmax over edges
    edgemax_kernel<<<(E_EDGES + 255) / 256, 256>>>(mlp_b);
    edgeexp_kernel<<<(E_EDGES + 255) / 256, 256>>>();
    edgeout_kernel<<<(E_EDGES + 255) / 256, 256>>>(v_vals, out);
}

// round 4
// speedup vs baseline: 4.6321x; 4.6321x over previous
#include <cuda_runtime.h>

#define N_NODES 50000
#define E_EDGES 800000
#define F_INN   512
#define HIDD    128

// ---------------- scratch (no allocs allowed) ----------------
__device__ float    g_u1[F_INN];       // gcn_w @ w1
__device__ float    g_u2[F_INN];       // gcn_w @ w2
__device__ float    g_beta;            // gcn_b.(w1+w2) + mlp_b
__device__ float    g_p1[N_NODES];     // feat[n].u1
__device__ float    g_p2[N_NODES];     // feat[n].u2
__device__ float    g_a[N_NODES];      // segment scatter of v*p1[col]
__device__ float    g_c[N_NODES];      // segment scatter of v*p2[col]
__device__ unsigned g_m[N_NODES];      // per-row max (ordered-uint)
__device__ float    g_s[N_NODES];      // per-row sum of exp
__device__ float    g_t[E_EDGES];      // per-edge temp, then exp
__device__ int      g_row[E_EDGES];    // normalized int32 rows
__device__ int      g_col[E_EDGES];    // normalized int32 cols
__device__ int      g_is64;            // index dtype flag

// ordered-uint encoding so unsigned atomicMax == float max
__device__ __forceinline__ unsigned enc_f(float f) {
    unsigned u = __float_as_uint(f);
    return u ^ ((u >> 31) ? 0xFFFFFFFFu : 0x80000000u);
}
__device__ __forceinline__ float dec_f(unsigned u) {
    return __uint_as_float(u ^ ((u >> 31) ? 0x80000000u : 0xFFFFFFFFu));
}

// ---------------- detect index dtype on-device ----------------
__global__ void detect_kernel(const void* __restrict__ idx) {
    const long long* p = (const long long*)idx;
    int is64 = 1;
    for (int i = 0; i < 16; i++) {
        long long v = p[i];
        if (v < 0 || v >= N_NODES) { is64 = 0; break; }
    }
    g_is64 = is64;
}

// ---------------- normalize indices to int32 ----------------
__global__ void convert_kernel(const void* __restrict__ idx) {
    int e = blockIdx.x * blockDim.x + threadIdx.x;
    if (e >= E_EDGES) return;
    if (g_is64) {
        const long long* p = (const long long*)idx;
        g_row[e] = (int)p[e];
        g_col[e] = (int)p[E_EDGES + e];
    } else {
        const int* p = (const int*)idx;
        g_row[e] = p[e];
        g_col[e] = p[E_EDGES + e];
    }
}

// ---------------- u1 = gcn_w @ w1, u2 = gcn_w @ w2 (tiny) ----------------
__global__ void u_kernel(const float* __restrict__ gcn_w,
                         const float* __restrict__ mlp_w) {
    int k = blockIdx.x * blockDim.x + threadIdx.x;   // 0..511
    if (k >= F_INN) return;
    const float* wrow = gcn_w + (size_t)k * HIDD;
    float s1 = 0.f, s2 = 0.f;
#pragma unroll 8
    for (int j = 0; j < HIDD; j++) {
        float w = wrow[j];
        s1 += w * mlp_w[j];
        s2 += w * mlp_w[HIDD + j];
    }
    g_u1[k] = s1;
    g_u2[k] = s2;
}

// ---------------- beta = gcn_b.(w1+w2) + mlp_b (one warp) ----------------
__global__ void beta_kernel(const float* __restrict__ gcn_b,
                            const float* __restrict__ mlp_w,
                            const float* __restrict__ mlp_b) {
    int lane = threadIdx.x;   // 32 threads
    float s = 0.f;
    for (int j = lane; j < HIDD; j += 32)
        s += gcn_b[j] * (mlp_w[j] + mlp_w[HIDD + j]);
#pragma unroll
    for (int o = 16; o > 0; o >>= 1) s += __shfl_xor_sync(0xFFFFFFFFu, s, o);
    if (lane == 0) g_beta = s + mlp_b[0];
}

// ---------------- init: zero a, c, m, s ----------------
__global__ void init_kernel() {
    int i = blockIdx.x * blockDim.x + threadIdx.x;
    if (i < N_NODES) { g_a[i] = 0.f; g_c[i] = 0.f; g_m[i] = 0u; g_s[i] = 0.f; }
}

// ---------------- p1[n] = feat[n].u1, p2[n] = feat[n].u2 ----------------
// one warp per node; streams feat once (102 MB) -> HBM-bound
__global__ __launch_bounds__(256) void p_kernel(const float* __restrict__ feat) {
    __shared__ float su1[F_INN];
    __shared__ float su2[F_INN];
    for (int i = threadIdx.x; i < F_INN; i += 256) {
        su1[i] = g_u1[i];
        su2[i] = g_u2[i];
    }
    __syncthreads();

    int n = blockIdx.x * 8 + (threadIdx.x >> 5);
    if (n >= N_NODES) return;
    int lane = threadIdx.x & 31;
    const float* frow = feat + (size_t)n * F_INN;
    float s1 = 0.f, s2 = 0.f;
#pragma unroll
    for (int ch = 0; ch < 4; ch++) {
        int o = ch * 128 + lane * 4;
        float4 f = *(const float4*)(frow + o);
        s1 += f.x * su1[o]     + f.y * su1[o + 1] + f.z * su1[o + 2] + f.w * su1[o + 3];
        s2 += f.x * su2[o]     + f.y * su2[o + 1] + f.z * su2[o + 2] + f.w * su2[o + 3];
    }
#pragma unroll
    for (int o = 16; o > 0; o >>= 1) {
        s1 += __shfl_xor_sync(0xFFFFFFFFu, s1, o);
        s2 += __shfl_xor_sync(0xFFFFFFFFu, s2, o);
    }
    if (lane == 0) { g_p1[n] = s1; g_p2[n] = s2; }
}

// ---------------- scalar edge scatter: a[row] += v*p1[col], c[row] += v*p2[col] ----------------
__global__ void scatter_kernel(const float* __restrict__ vals) {
    int e = blockIdx.x * blockDim.x + threadIdx.x;
    if (e >= E_EDGES) return;
    int r = g_row[e];
    int c = g_col[e];
    float v = vals[e];
    atomicAdd(&g_a[r], v * g_p1[c]);
    atomicAdd(&g_c[r], v * g_p2[c]);
}

// ---------------- temp per edge + segment max ----------------
__global__ void edgemax_kernel() {
    int e = blockIdx.x * blockDim.x + threadIdx.x;
    if (e >= E_EDGES) return;
    int r = g_row[e];
    int c = g_col[e];
    float t = g_a[r] + g_c[c] + g_beta;
    g_t[e] = t;
    atomicMax(&g_m[r], enc_f(t));
}

// ---------------- exp + segment sum ----------------
__global__ void edgeexp_kernel() {
    int e = blockIdx.x * blockDim.x + threadIdx.x;
    if (e >= E_EDGES) return;
    int r = g_row[e];
    float m = dec_f(g_m[r]);
    float ex = expf(g_t[e] - m);
    g_t[e] = ex;
    atomicAdd(&g_s[r], ex);
}

// ---------------- normalize + add v_ori ----------------
__global__ void edgeout_kernel(const float* __restrict__ vals,
                               float* __restrict__ out) {
    int e = blockIdx.x * blockDim.x + threadIdx.x;
    if (e >= E_EDGES) return;
    int r = g_row[e];
    out[e] = vals[e] + g_t[e] / g_s[r];
}

// ---------------- launch ----------------
extern "C" void kernel_launch(void* const* d_in, const int* in_sizes, int n_in,
                              void* d_out, int out_size) {
    const float* v_vals = (const float*)d_in[0];
    const float* feat   = (const float*)d_in[1];
    const void*  idx    = d_in[2];
    const float* gcn_w  = (const float*)d_in[n_in - 4];   // 512*128
    const float* gcn_b  = (const float*)d_in[n_in - 3];   // 128
    const float* mlp_w  = (const float*)d_in[n_in - 2];   // 256
    const float* mlp_b  = (const float*)d_in[n_in - 1];   // 1
    float*       out    = (float*)d_out;

    detect_kernel<<<1, 1>>>(idx);
    convert_kernel<<<(E_EDGES + 255) / 256, 256>>>(idx);

    u_kernel<<<2, 256>>>(gcn_w, mlp_w);
    beta_kernel<<<1, 32>>>(gcn_b, mlp_w, mlp_b);
    init_kernel<<<(N_NODES + 255) / 256, 256>>>();

    p_kernel<<<(N_NODES + 7) / 8, 256>>>(feat);

    scatter_kernel<<<(E_EDGES + 255) / 256, 256>>>(v_vals);

    edgemax_kernel<<<(E_EDGES + 255) / 256, 256>>>();
    edgeexp_kernel<<<(E_EDGES + 255) / 256, 256>>>();
    edgeout_kernel<<<(E_EDGES + 255) / 256, 256>>>(v_vals, out);
}

// round 5
// speedup vs baseline: 5.4474x; 1.1760x over previous
#include <cuda_runtime.h>

#define N_NODES 50000
#define E_EDGES 800000
#define F_INN   512
#define HIDD    128

// ---------------- scratch (no allocs allowed) ----------------
__device__ float g_u1[F_INN];       // gcn_w @ w1
__device__ float g_u2[F_INN];       // gcn_w @ w2
__device__ float g_beta;            // gcn_b.(w1+w2) + mlp_b
__device__ float g_p1[N_NODES];     // feat[n].u1
__device__ float g_p2[N_NODES];     // feat[n].u2
__device__ float g_a[N_NODES];      // segment scatter of v*p1[col]
__device__ float g_c[N_NODES];      // segment scatter of v*p2[col]
__device__ float g_s[N_NODES];      // per-row sum of exp
__device__ int   g_row[E_EDGES];    // normalized int32 rows
__device__ int   g_col[E_EDGES];    // normalized int32 cols

// Per-block index-dtype detection: reads 16 leading int64 words (L2-cached,
// identical across blocks). int64 indices are all in [0, N); int32 data
// reinterpreted as int64 is out of range almost surely.
__device__ __forceinline__ int detect_is64(const void* idx) {
    const long long* p = (const long long*)idx;
    int is64 = 1;
#pragma unroll
    for (int i = 0; i < 16; i++) {
        long long v = p[i];
        if (v < 0 || v >= N_NODES) { is64 = 0; break; }
    }
    return is64;
}

// ---------------- K1: setup — u1/u2, beta, zero a/c/s ----------------
// blockIdx 0..1   : u1/u2 (512 rows of gcn_w, 128-dot each)
// blockIdx 2      : beta (one warp)
// blockIdx 3..    : zero-init a, c, s
__global__ __launch_bounds__(256) void setup_kernel(const float* __restrict__ gcn_w,
                                                    const float* __restrict__ gcn_b,
                                                    const float* __restrict__ mlp_w,
                                                    const float* __restrict__ mlp_b) {
    int b = blockIdx.x;
    if (b < 2) {
        int k = b * 256 + threadIdx.x;           // 0..511
        const float* wrow = gcn_w + (size_t)k * HIDD;
        float s1 = 0.f, s2 = 0.f;
#pragma unroll 8
        for (int j = 0; j < HIDD; j++) {
            float w = wrow[j];
            s1 += w * mlp_w[j];
            s2 += w * mlp_w[HIDD + j];
        }
        g_u1[k] = s1;
        g_u2[k] = s2;
    } else if (b == 2) {
        if (threadIdx.x < 32) {
            int lane = threadIdx.x;
            float s = 0.f;
            for (int j = lane; j < HIDD; j += 32)
                s += gcn_b[j] * (mlp_w[j] + mlp_w[HIDD + j]);
#pragma unroll
            for (int o = 16; o > 0; o >>= 1) s += __shfl_xor_sync(0xFFFFFFFFu, s, o);
            if (lane == 0) g_beta = s + mlp_b[0];
        }
    } else {
        int i = (b - 3) * 256 + threadIdx.x;
        if (i < N_NODES) { g_a[i] = 0.f; g_c[i] = 0.f; g_s[i] = 0.f; }
    }
}

// ---------------- K2: p1[n]=feat[n].u1, p2[n]=feat[n].u2 (warp/node) ----------------
__global__ __launch_bounds__(256) void p_kernel(const float* __restrict__ feat) {
    __shared__ float su1[F_INN];
    __shared__ float su2[F_INN];
    for (int i = threadIdx.x; i < F_INN; i += 256) {
        su1[i] = g_u1[i];
        su2[i] = g_u2[i];
    }
    __syncthreads();

    int n = blockIdx.x * 8 + (threadIdx.x >> 5);
    if (n >= N_NODES) return;
    int lane = threadIdx.x & 31;
    const float* frow = feat + (size_t)n * F_INN;
    float s1 = 0.f, s2 = 0.f;
#pragma unroll
    for (int ch = 0; ch < 4; ch++) {
        int o = ch * 128 + lane * 4;
        float4 f = *(const float4*)(frow + o);
        s1 += f.x * su1[o] + f.y * su1[o + 1] + f.z * su1[o + 2] + f.w * su1[o + 3];
        s2 += f.x * su2[o] + f.y * su2[o + 1] + f.z * su2[o + 2] + f.w * su2[o + 3];
    }
#pragma unroll
    for (int o = 16; o > 0; o >>= 1) {
        s1 += __shfl_xor_sync(0xFFFFFFFFu, s1, o);
        s2 += __shfl_xor_sync(0xFFFFFFFFu, s2, o);
    }
    if (lane == 0) { g_p1[n] = s1; g_p2[n] = s2; }
}

// ---------------- K3: convert indices + scatter a/c ----------------
__global__ void scatter_kernel(const void* __restrict__ idx,
                               const float* __restrict__ vals) {
    int e = blockIdx.x * blockDim.x + threadIdx.x;
    if (e >= E_EDGES) return;
    int r, c;
    if (detect_is64(idx)) {
        const long long* p = (const long long*)idx;
        r = (int)p[e];
        c = (int)p[E_EDGES + e];
    } else {
        const int* p = (const int*)idx;
        r = p[e];
        c = p[E_EDGES + e];
    }
    g_row[e] = r;
    g_col[e] = c;
    float v = vals[e];
    atomicAdd(&g_a[r], v * g_p1[c]);
    atomicAdd(&g_c[r], v * g_p2[c]);
}

// ---------------- K4: sum of exp per row (no max shift needed) ----------------
__global__ void sumexp_kernel() {
    int e = blockIdx.x * blockDim.x + threadIdx.x;
    if (e >= E_EDGES) return;
    int r = g_row[e];
    int c = g_col[e];
    float ex = expf(g_a[r] + g_c[c] + g_beta);
    atomicAdd(&g_s[r], ex);
}

// ---------------- K5: out = v + exp(t)/s[row] ----------------
__global__ void out_kernel(const float* __restrict__ vals,
                           float* __restrict__ out) {
    int e = blockIdx.x * blockDim.x + threadIdx.x;
    if (e >= E_EDGES) return;
    int r = g_row[e];
    int c = g_col[e];
    float ex = expf(g_a[r] + g_c[c] + g_beta);   // identical ops as K4
    out[e] = vals[e] + ex / g_s[r];
}

// ---------------- launch ----------------
extern "C" void kernel_launch(void* const* d_in, const int* in_sizes, int n_in,
                              void* d_out, int out_size) {
    const float* v_vals = (const float*)d_in[0];
    const float* feat   = (const float*)d_in[1];
    const void*  idx    = d_in[2];
    const float* gcn_w  = (const float*)d_in[n_in - 4];   // 512*128
    const float* gcn_b  = (const float*)d_in[n_in - 3];   // 128
    const float* mlp_w  = (const float*)d_in[n_in - 2];   // 256
    const float* mlp_b  = (const float*)d_in[n_in - 1];   // 1
    float*       out    = (float*)d_out;

    int init_blocks = 3 + (N_NODES + 255) / 256;
    setup_kernel<<<init_blocks, 256>>>(gcn_w, gcn_b, mlp_w, mlp_b);

    p_kernel<<<(N_NODES + 7) / 8, 256>>>(feat);

    scatter_kernel<<<(E_EDGES + 255) / 256, 256>>>(idx, v_vals);
    sumexp_kernel<<<(E_EDGES + 255) / 256, 256>>>();
    out_kernel<<<(E_EDGES + 255) / 256, 256>>>(v_vals, out);
}